// round 13
// baseline (speedup 1.0000x reference)
#include <cuda_runtime.h>
#include <cstdint>

#define BB 16
#define SS 2048
#define DD 1024
#define HH 64
#define MM (BB*SS)

// Scratch (no cudaMalloc allowed). All pre-rounded to tf32 (rna) at producer.
// k-dims stored perm8-permuted within groups of 8 so fragment pairs are adjacent:
//   g_q/g_k: head-dim d permuted; g_vt: key index (within row) permuted;
//   g_wt: feature k permuted.
__device__ float g_q [MM*HH];      // [b*2048+s][64]   (d permuted)
__device__ float g_k [MM*HH];      // [b*2048+s][64]   (d permuted)
__device__ float g_vt[MM*HH];      // [b*64+d][2048]   (s permuted within 8)
__device__ float g_wt[3*HH*DD];    // [mat][n*1024+k]  (k permuted within 8)

// ---------------------------------------------------------------------------
// helpers
// ---------------------------------------------------------------------------
static __device__ __forceinline__ float rna(float f) {
    uint32_t r;
    asm("cvt.rna.tf32.f32 %0, %1;" : "=r"(r) : "f"(f));
    return __uint_as_float(r);
}
static __device__ __forceinline__ int perm8(int k) {     // stored position of orig k
    return ((k & 3) << 1) | ((k >> 2) & 1);
}
static __device__ __forceinline__ uint32_t smem_u32(const void* p) {
    uint32_t a;
    asm("{ .reg .u64 t; cvta.to.shared.u64 t, %1; cvt.u32.u64 %0, t; }"
        : "=r"(a) : "l"(p));
    return a;
}
#define CP16(dst, src) \
    asm volatile("cp.async.ca.shared.global [%0], [%1], 16;" \
                 :: "r"(dst), "l"(src) : "memory")
#define CP_COMMIT() asm volatile("cp.async.commit_group;" ::: "memory")
#define CP_WAIT1()  asm volatile("cp.async.wait_group 1;" ::: "memory")
#define CP_WAIT0()  asm volatile("cp.async.wait_group 0;" ::: "memory")

// D += A(16x8) * B(8x8); tf32 inputs, f32 accum.
// A: a0=(g,tg) a1=(g+8,tg) a2=(g,tg+4) a3=(g+8,tg+4)
// B: b0=(k=tg,n=g) b1=(k=tg+4,n=g)
// C: c0=(g,2tg) c1=(g,2tg+1) c2=(g+8,2tg) c3=(g+8,2tg+1)
static __device__ __forceinline__ void mma8(float* d, const float* a, const float* b) {
    asm volatile(
        "mma.sync.aligned.m16n8k8.row.col.f32.tf32.tf32.f32 "
        "{%0,%1,%2,%3}, {%4,%5,%6,%7}, {%8,%9}, {%0,%1,%2,%3};"
        : "+f"(d[0]), "+f"(d[1]), "+f"(d[2]), "+f"(d[3])
        : "r"(__float_as_uint(a[0])), "r"(__float_as_uint(a[1])),
          "r"(__float_as_uint(a[2])), "r"(__float_as_uint(a[3])),
          "r"(__float_as_uint(b[0])), "r"(__float_as_uint(b[1])));
}

// ---------------------------------------------------------------------------
// Kernel 0: transpose + tf32-round + k-permute W -> g_wt[mat][n*1024+k']
// ---------------------------------------------------------------------------
__global__ __launch_bounds__(128) void transpose_w(
    const float* __restrict__ Wq, const float* __restrict__ Wk,
    const float* __restrict__ Wv)
{
    int mat = blockIdx.x >> 4, kc = blockIdx.x & 15;
    const float* W = (mat == 0) ? Wq : (mat == 1) ? Wk : Wv;
    int tid = threadIdx.x;
    #pragma unroll
    for (int i = 0; i < 8; i++) {
        int lin = tid + i * 128;
        int k   = lin >> 4;
        int n4  = lin & 15;
        float4 v = *(const float4*)(W + (size_t)(kc * 64 + k) * HH + n4 * 4);
        int kg = kc * 64 + k;
        int kp = (kg & ~7) | perm8(kg & 7);
        float* dst = g_wt + (size_t)mat * HH * DD;
        dst[(n4*4+0) * DD + kp] = rna(v.x);
        dst[(n4*4+1) * DD + kp] = rna(v.y);
        dst[(n4*4+2) * DD + kp] = rna(v.z);
        dst[(n4*4+3) * DD + kp] = rna(v.w);
    }
}

// ---------------------------------------------------------------------------
// Kernel 1: fused QKV projection, tf32 mma.sync, cp.async double-buffered.
// 512 threads (16 warps): warp = 16 rows (wr=w&7) x half nt-range (wn=w>>3).
// K chunks of 32. dyn smem (floats): X buf0 0 / buf1 4608 (128x36) |
// W buf0 9216 / buf1 16128 (192x36). Epilogue reuses [0..8704).
// ---------------------------------------------------------------------------
#define XSTR 36
#define PROJ_SMEM (23040 * 4)

__global__ __launch_bounds__(512) void proj_kernel(const float* __restrict__ x)
{
    extern __shared__ float psm[];
    const uint32_t SB = smem_u32(psm);

    const int tid  = threadIdx.x;
    const int w    = tid >> 5;
    const int lane = tid & 31;
    const int g    = lane >> 2;
    const int tg   = lane & 3;
    const int wr   = w & 7;     // row-tile 16*wr
    const int wn   = w >> 3;    // nt offset 4*wn
    const int m0   = blockIdx.x * 128;

    auto stage = [&](int c, int buf) {
        {   // X chunk: 128 x 32 = 1024 float4, 2 per thread
            #pragma unroll
            for (int i = 0; i < 2; i++) {
                int lin = tid + i * 512;
                int row = lin >> 3, c4 = lin & 7;
                const float* src = x + (size_t)(m0 + row) * DD + c * 32 + c4 * 4;
                CP16(SB + (buf * 4608 + row * XSTR + c4 * 4) * 4, src);
            }
        }
        {   // W chunks: 3 x 64 x 32 = 1536 float4, 3 per thread
            #pragma unroll
            for (int i = 0; i < 3; i++) {
                int lin = tid + i * 512;
                int mat = lin >> 9, rem = lin & 511;
                int n = rem >> 3, c4 = rem & 7;
                const float* src = g_wt + (size_t)mat * HH * DD + (size_t)n * DD + c * 32 + c4 * 4;
                CP16(SB + (9216 + buf * 6912 + (mat * 64 + n) * XSTR + c4 * 4) * 4, src);
            }
        }
    };

    float acc[3][4][4];
    #pragma unroll
    for (int m = 0; m < 3; m++)
        #pragma unroll
        for (int n = 0; n < 4; n++)
            #pragma unroll
            for (int i = 0; i < 4; i++) acc[m][n][i] = 0.f;

    stage(0, 0); CP_COMMIT();

    for (int c = 0; c < 32; c++) {
        __syncthreads();
        if (c + 1 < 32) { stage(c + 1, (c + 1) & 1); CP_COMMIT(); CP_WAIT1(); }
        else            { CP_WAIT0(); }
        __syncthreads();

        const float* Xb = psm + (c & 1) * 4608;
        const float* Wb = psm + 9216 + (c & 1) * 6912;
        const int r = 16 * wr + g;
        #pragma unroll
        for (int ks = 0; ks < 4; ks++) {
            float a[4];
            a[0] = rna(Xb[r       * XSTR + ks*8 + tg]);
            a[1] = rna(Xb[(r + 8) * XSTR + ks*8 + tg]);
            a[2] = rna(Xb[r       * XSTR + ks*8 + tg + 4]);
            a[3] = rna(Xb[(r + 8) * XSTR + ks*8 + tg + 4]);
            #pragma unroll
            for (int mat = 0; mat < 3; mat++)
                #pragma unroll
                for (int nti = 0; nti < 4; nti++) {
                    float2 bv = *(const float2*)&Wb[(mat*64 + (4*wn + nti)*8 + g) * XSTR
                                                    + ks*8 + 2*tg];
                    float bbv[2] = {bv.x, bv.y};
                    mma8(acc[mat][nti], a, bbv);
                }
        }
    }

    // ---- epilogue: rna-round; q/k stored d-permuted, v stored s-permuted ----
    const int bq = m0 >> 11;
    const int s0 = m0 & 2047;
    const int P0 = perm8(2*tg), P1 = perm8(2*tg + 1);

    #pragma unroll
    for (int mat = 0; mat < 2; mat++) {
        __syncthreads();
        #pragma unroll
        for (int nti = 0; nti < 4; nti++) {
            int dbase = (4*wn + nti) * 8;
            int r = 16*wr + g;
            psm[r       * 68 + dbase + P0] = rna(acc[mat][nti][0]);
            psm[r       * 68 + dbase + P1] = rna(acc[mat][nti][1]);
            psm[(r + 8) * 68 + dbase + P0] = rna(acc[mat][nti][2]);
            psm[(r + 8) * 68 + dbase + P1] = rna(acc[mat][nti][3]);
        }
        __syncthreads();
        float* dst = (mat == 0) ? g_q : g_k;
        int row = tid >> 2, q4 = (tid & 3) * 16;
        #pragma unroll
        for (int i = 0; i < 4; i++) {
            float4 v = *(float4*)&psm[row * 68 + q4 + i * 4];
            *(float4*)&dst[(size_t)(m0 + row) * HH + q4 + i * 4] = v;
        }
    }

    __syncthreads();
    {
        int sp0 = 16*wr + perm8(g);
        int sp1 = sp0 + 8;
        #pragma unroll
        for (int nti = 0; nti < 4; nti++) {   // psm as [64 d][132]
            int dbase = (4*wn + nti) * 8;
            psm[(dbase + 2*tg)     * 132 + sp0] = rna(acc[2][nti][0]);
            psm[(dbase + 2*tg + 1) * 132 + sp0] = rna(acc[2][nti][1]);
            psm[(dbase + 2*tg)     * 132 + sp1] = rna(acc[2][nti][2]);
            psm[(dbase + 2*tg + 1) * 132 + sp1] = rna(acc[2][nti][3]);
        }
    }
    __syncthreads();
    {
        int d = tid >> 3, sc = (tid & 7) * 16;
        #pragma unroll
        for (int i = 0; i < 4; i++) {
            float4 v = *(float4*)&psm[d * 132 + sc + i * 4];
            *(float4*)&g_vt[((size_t)bq * HH + d) * SS + s0 + sc + i * 4] = v;
        }
    }
}

// ---------------------------------------------------------------------------
// Kernel 2: causal flash attention, tf32 mma.sync, float2 fragment loads.
// 128 threads; q-tile 128 rows; kv tiles 64, cp.async double-buffered.
// P fragment->fragment via shuffles. smem (floats): Qs 0 (128x68) |
// K buf0 8704 / buf1 13056 | V buf0 17408 / buf1 21760 (each 64x68).
// ---------------------------------------------------------------------------
#define ATTN_SMEM (26112 * 4)

__global__ __launch_bounds__(128) void attn_kernel(float* __restrict__ out)
{
    extern __shared__ float sm[];
    const uint32_t SB = smem_u32(sm);

    const int tid  = threadIdx.x;
    const int w    = tid >> 5;
    const int lane = tid & 31;
    const int g    = lane >> 2;
    const int tg   = lane & 3;

    // load-balance remap
    int pos = blockIdx.x, rank;
    if      (pos < 108) rank = 40 + pos;
    else if (pos < 148) rank = pos - 108;
    else                rank = 255 - (pos - 148);
    const int qt = 15 - (rank >> 4);
    const int b  = rank & 15;

    auto stageKV = [&](int kt2, int buf) {
        int row = tid >> 1, hh = (tid & 1) * 32;
        const float* ks = g_k + ((size_t)b * SS + kt2 * 64 + row) * HH + hh;
        uint32_t kd = SB + (8704 + buf * 4352 + row * 68 + hh) * 4;
        #pragma unroll
        for (int i = 0; i < 8; i++) CP16(kd + i * 16, ks + i * 4);
        const float* vs = g_vt + ((size_t)b * HH + row) * SS + kt2 * 64 + hh;
        uint32_t vd = SB + (17408 + buf * 4352 + row * 68 + hh) * 4;
        #pragma unroll
        for (int i = 0; i < 8; i++) CP16(vd + i * 16, vs + i * 4);
    };

    {   // Q (pre-rounded, d-permuted) via cp.async
        const float* src = g_q + ((size_t)b * SS + qt * 128 + tid) * HH;
        uint32_t dst = SB + (tid * 68) * 4;
        #pragma unroll
        for (int i = 0; i < 16; i++) CP16(dst + i * 16, src + i * 4);
    }
    CP_COMMIT();
    stageKV(0, 0); CP_COMMIT();

    float oacc[2][8][4];
    #pragma unroll
    for (int m = 0; m < 2; m++)
        #pragma unroll
        for (int n = 0; n < 8; n++)
            #pragma unroll
            for (int i = 0; i < 4; i++) oacc[m][n][i] = 0.f;
    float lsum[2][2] = {{0.f, 0.f}, {0.f, 0.f}};

    const float scl = 1.0f / 64.0f;
    const int rbase = qt * 128 + 32 * w + g;
    const int ktmax = 2 * qt + 1;
    const float* Qs = sm;

    for (int kt = 0; kt <= ktmax; kt++) {
        __syncthreads();
        if (kt + 1 <= ktmax) { stageKV(kt + 1, (kt + 1) & 1); CP_COMMIT(); CP_WAIT1(); }
        else                 { CP_WAIT0(); }
        __syncthreads();

        const float* Ks = sm + 8704  + (kt & 1) * 4352;
        const float* Vt = sm + 17408 + (kt & 1) * 4352;

        // ---- S = Q K^T (float2 fragment loads; d permuted in storage) ----
        float p[2][8][4];
        #pragma unroll
        for (int m = 0; m < 2; m++)
            #pragma unroll
            for (int n = 0; n < 8; n++)
                #pragma unroll
                for (int i = 0; i < 4; i++) p[m][n][i] = 0.f;

        #pragma unroll
        for (int ks = 0; ks < 8; ks++) {
            float a[2][4];
            #pragma unroll
            for (int mt = 0; mt < 2; mt++) {
                int r = 32*w + 16*mt + g;
                float2 qa = *(const float2*)&Qs[r       * 68 + ks*8 + 2*tg];
                float2 qb = *(const float2*)&Qs[(r + 8) * 68 + ks*8 + 2*tg];
                a[mt][0] = qa.x; a[mt][1] = qb.x;
                a[mt][2] = qa.y; a[mt][3] = qb.y;
            }
            #pragma unroll
            for (int nt = 0; nt < 8; nt++) {
                float2 kb = *(const float2*)&Ks[(nt*8 + g) * 68 + ks*8 + 2*tg];
                float bbv[2] = {kb.x, kb.y};
                mma8(p[0][nt], a[0], bbv);
                mma8(p[1][nt], a[1], bbv);
            }
        }

        // ---- mask + exp (rna) in place (S columns j are natural) ----
        #pragma unroll
        for (int mt = 0; mt < 2; mt++) {
            int rg0 = rbase + 16*mt;
            int rg1 = rg0 + 8;
            #pragma unroll
            for (int nt = 0; nt < 8; nt++) {
                int c0 = kt*64 + nt*8 + 2*tg;
                float p0 = (c0     <= rg0) ? rna(__expf(p[mt][nt][0] * scl)) : 0.f;
                float p1 = (c0 + 1 <= rg0) ? rna(__expf(p[mt][nt][1] * scl)) : 0.f;
                float p2 = (c0     <= rg1) ? rna(__expf(p[mt][nt][2] * scl)) : 0.f;
                float p3 = (c0 + 1 <= rg1) ? rna(__expf(p[mt][nt][3] * scl)) : 0.f;
                lsum[mt][0] += p0 + p1;
                lsum[mt][1] += p2 + p3;
                p[mt][nt][0] = p0; p[mt][nt][1] = p1;
                p[mt][nt][2] = p2; p[mt][nt][3] = p3;
            }
        }

        // ---- O += P V : shuffles for A; float2 B loads (Vt j permuted) ----
        {
            const int s0l = (lane & 28) | (tg >> 1);
            const int s1l = s0l + 2;
            const bool odd = (tg & 1);
            #pragma unroll
            for (int ks = 0; ks < 8; ks++) {
                float a[2][4];
                #pragma unroll
                for (int mt = 0; mt < 2; mt++) {
                    float c0 = p[mt][ks][0], c1 = p[mt][ks][1];
                    float c2 = p[mt][ks][2], c3 = p[mt][ks][3];
                    float v0 = __shfl_sync(0xffffffffu, c0, s0l);
                    float v1 = __shfl_sync(0xffffffffu, c1, s0l);
                    float v2 = __shfl_sync(0xffffffffu, c2, s0l);
                    float v3 = __shfl_sync(0xffffffffu, c3, s0l);
                    float u0 = __shfl_sync(0xffffffffu, c0, s1l);
                    float u1 = __shfl_sync(0xffffffffu, c1, s1l);
                    float u2 = __shfl_sync(0xffffffffu, c2, s1l);
                    float u3 = __shfl_sync(0xffffffffu, c3, s1l);
                    a[mt][0] = odd ? v1 : v0;
                    a[mt][1] = odd ? v3 : v2;
                    a[mt][2] = odd ? u1 : u0;
                    a[mt][3] = odd ? u3 : u2;
                }
                #pragma unroll
                for (int nt = 0; nt < 8; nt++) {
                    float2 vb = *(const float2*)&Vt[(nt*8 + g) * 68 + ks*8 + 2*tg];
                    float bbv[2] = {vb.x, vb.y};
                    mma8(oacc[0][nt], a[0], bbv);
                    mma8(oacc[1][nt], a[1], bbv);
                }
            }
        }
    }

    // reduce l across the 4 quad lanes
    #pragma unroll
    for (int mt = 0; mt < 2; mt++)
        #pragma unroll
        for (int h = 0; h < 2; h++) {
            float v = lsum[mt][h];
            v += __shfl_xor_sync(0xffffffffu, v, 1);
            v += __shfl_xor_sync(0xffffffffu, v, 2);
            lsum[mt][h] = v;
        }

    // normalize + write (output d natural: Vt rows unpermuted)
    #pragma unroll
    for (int mt = 0; mt < 2; mt++) {
        float i0 = 1.0f / lsum[mt][0];
        float i1 = 1.0f / lsum[mt][1];
        int r = qt*128 + 32*w + 16*mt + g;
        float* o0 = out + ((size_t)b * SS + r)     * HH;
        float* o1 = out + ((size_t)b * SS + r + 8) * HH;
        #pragma unroll
        for (int nt = 0; nt < 8; nt++) {
            *(float2*)&o0[nt*8 + 2*tg] =
                make_float2(oacc[mt][nt][0] * i0, oacc[mt][nt][1] * i0);
            *(float2*)&o1[nt*8 + 2*tg] =
                make_float2(oacc[mt][nt][2] * i1, oacc[mt][nt][3] * i1);
        }
    }
}

// ---------------------------------------------------------------------------
extern "C" void kernel_launch(void* const* d_in, const int* in_sizes, int n_in,
                              void* d_out, int out_size)
{
    const float* x  = (const float*)d_in[0];
    const float* Wq = (const float*)d_in[1];
    const float* Wk = (const float*)d_in[2];
    const float* Wv = (const float*)d_in[3];
    float* out = (float*)d_out;
    (void)in_sizes; (void)n_in; (void)out_size;

    cudaFuncSetAttribute(proj_kernel, cudaFuncAttributeMaxDynamicSharedMemorySize,
                         PROJ_SMEM);
    cudaFuncSetAttribute(attn_kernel, cudaFuncAttributeMaxDynamicSharedMemorySize,
                         ATTN_SMEM);

    transpose_w<<<48, 128>>>(Wq, Wk, Wv);
    proj_kernel<<<MM / 128, 512, PROJ_SMEM>>>(x);
    attn_kernel<<<256, 128, ATTN_SMEM>>>(out);
}

// round 14
// speedup vs baseline: 1.2139x; 1.2139x over previous
#include <cuda_runtime.h>
#include <cstdint>

#define BB 16
#define SS 2048
#define DD 1024
#define HH 64
#define MM (BB*SS)

// Scratch (no cudaMalloc allowed). All pre-rounded to tf32 (rna) at producer.
__device__ float g_q [MM*HH];      // [b*2048+s][64]
__device__ float g_k [MM*HH];      // [b*2048+s][64]
__device__ float g_vt[MM*HH];      // [b*64+d][2048]  (V transposed)
__device__ float g_wt[3*HH*DD];    // [mat][n*1024+k] (W transposed)

// ---------------------------------------------------------------------------
// helpers
// ---------------------------------------------------------------------------
static __device__ __forceinline__ float rna(float f) {
    uint32_t r;
    asm("cvt.rna.tf32.f32 %0, %1;" : "=r"(r) : "f"(f));
    return __uint_as_float(r);
}
static __device__ __forceinline__ uint32_t smem_u32(const void* p) {
    uint32_t a;
    asm("{ .reg .u64 t; cvta.to.shared.u64 t, %1; cvt.u32.u64 %0, t; }"
        : "=r"(a) : "l"(p));
    return a;
}
#define CP16(dst, src) \
    asm volatile("cp.async.ca.shared.global [%0], [%1], 16;" \
                 :: "r"(dst), "l"(src) : "memory")
#define CP_COMMIT() asm volatile("cp.async.commit_group;" ::: "memory")
#define CP_WAIT1()  asm volatile("cp.async.wait_group 1;" ::: "memory")
#define CP_WAIT0()  asm volatile("cp.async.wait_group 0;" ::: "memory")

// D += A(16x8) * B(8x8); tf32 inputs, f32 accum.
// A: a0=(g,tg) a1=(g+8,tg) a2=(g,tg+4) a3=(g+8,tg+4)
// B: b0=(k=tg,n=g) b1=(k=tg+4,n=g)
// C: c0=(g,2tg) c1=(g,2tg+1) c2=(g+8,2tg) c3=(g+8,2tg+1)
static __device__ __forceinline__ void mma8(float* d, const float* a, const float* b) {
    asm volatile(
        "mma.sync.aligned.m16n8k8.row.col.f32.tf32.tf32.f32 "
        "{%0,%1,%2,%3}, {%4,%5,%6,%7}, {%8,%9}, {%0,%1,%2,%3};"
        : "+f"(d[0]), "+f"(d[1]), "+f"(d[2]), "+f"(d[3])
        : "r"(__float_as_uint(a[0])), "r"(__float_as_uint(a[1])),
          "r"(__float_as_uint(a[2])), "r"(__float_as_uint(a[3])),
          "r"(__float_as_uint(b[0])), "r"(__float_as_uint(b[1])));
}

// ---------------------------------------------------------------------------
// Kernel 0: transpose + tf32-round W -> g_wt[mat][n*1024+k]
// ---------------------------------------------------------------------------
__global__ __launch_bounds__(128) void transpose_w(
    const float* __restrict__ Wq, const float* __restrict__ Wk,
    const float* __restrict__ Wv)
{
    int mat = blockIdx.x >> 4, kc = blockIdx.x & 15;
    const float* W = (mat == 0) ? Wq : (mat == 1) ? Wk : Wv;
    int tid = threadIdx.x;
    #pragma unroll
    for (int i = 0; i < 8; i++) {
        int lin = tid + i * 128;
        int k   = lin >> 4;
        int n4  = lin & 15;
        float4 v = *(const float4*)(W + (size_t)(kc * 64 + k) * HH + n4 * 4);
        int kg = kc * 64 + k;
        float* dst = g_wt + (size_t)mat * HH * DD;
        dst[(n4*4+0) * DD + kg] = rna(v.x);
        dst[(n4*4+1) * DD + kg] = rna(v.y);
        dst[(n4*4+2) * DD + kg] = rna(v.z);
        dst[(n4*4+3) * DD + kg] = rna(v.w);
    }
}

// ---------------------------------------------------------------------------
// Kernel 1: fused QKV projection, tf32 mma.sync, cp.async double-buffered.
// 256 threads, tile 128 rows x (3x64) cols, K chunks of 32.
// dyn smem (floats): X buf0 0 / buf1 4608 (128x36) | W buf0 9216 / buf1 16128
// (192x36). Epilogue reuses [0..8704).
// ---------------------------------------------------------------------------
#define XSTR 36
#define PROJ_SMEM (23040 * 4)

__global__ __launch_bounds__(256) void proj_kernel(const float* __restrict__ x)
{
    extern __shared__ float psm[];
    const uint32_t SB = smem_u32(psm);

    const int tid  = threadIdx.x;
    const int w    = tid >> 5;
    const int lane = tid & 31;
    const int g    = lane >> 2;
    const int tg   = lane & 3;
    const int m0   = blockIdx.x * 128;

    // staging helpers (pure copies; X rounded at fragment load, W pre-rounded)
    auto stage = [&](int c, int buf) {
        {   // X chunk: 128 x 32 = 1024 float4, 4 per thread
            int row = tid >> 1, kq = (tid & 1) * 16;
            const float* src = x + (size_t)(m0 + row) * DD + c * 32 + kq;
            uint32_t dst = SB + (buf * 4608 + row * XSTR + kq) * 4;
            #pragma unroll
            for (int i = 0; i < 4; i++) CP16(dst + i * 16, src + i * 4);
        }
        {   // W chunks: 3 x 64 x 32 = 1536 float4, 6 per thread
            int n = tid >> 2, kq = (tid & 3) * 8;
            #pragma unroll
            for (int mat = 0; mat < 3; mat++) {
                const float* src = g_wt + (size_t)mat * HH * DD + (size_t)n * DD + c * 32 + kq;
                uint32_t dst = SB + (9216 + buf * 6912 + (mat * 64 + n) * XSTR + kq) * 4;
                CP16(dst, src);
                CP16(dst + 16, src + 4);
            }
        }
    };

    float acc[3][8][4];
    #pragma unroll
    for (int m = 0; m < 3; m++)
        #pragma unroll
        for (int n = 0; n < 8; n++)
            #pragma unroll
            for (int i = 0; i < 4; i++) acc[m][n][i] = 0.f;

    stage(0, 0); CP_COMMIT();

    for (int c = 0; c < 32; c++) {
        __syncthreads();   // prior iter's fragment reads of the refill buffer done
        if (c + 1 < 32) { stage(c + 1, (c + 1) & 1); CP_COMMIT(); CP_WAIT1(); }
        else            { CP_WAIT0(); }
        __syncthreads();   // chunk c visible

        const float* Xb = psm + (c & 1) * 4608;
        const float* Wb = psm + 9216 + (c & 1) * 6912;
        #pragma unroll
        for (int ks = 0; ks < 4; ks++) {
            float a[4];
            a[0] = rna(Xb[(16*w + g)     * XSTR + ks*8 + tg]);
            a[1] = rna(Xb[(16*w + g + 8) * XSTR + ks*8 + tg]);
            a[2] = rna(Xb[(16*w + g)     * XSTR + ks*8 + tg + 4]);
            a[3] = rna(Xb[(16*w + g + 8) * XSTR + ks*8 + tg + 4]);
            #pragma unroll
            for (int mat = 0; mat < 3; mat++)
                #pragma unroll
                for (int nt = 0; nt < 8; nt++) {
                    float bb[2];
                    bb[0] = Wb[(mat*64 + nt*8 + g) * XSTR + ks*8 + tg];
                    bb[1] = Wb[(mat*64 + nt*8 + g) * XSTR + ks*8 + tg + 4];
                    mma8(acc[mat][nt], a, bb);
                }
        }
    }

    // ---- epilogue: rna-round everything (consumed only as tf32 inputs) ----
    const int bq = m0 >> 11;
    const int s0 = m0 & 2047;

    #pragma unroll
    for (int mat = 0; mat < 2; mat++) {
        __syncthreads();
        #pragma unroll
        for (int nt = 0; nt < 8; nt++) {
            *(float2*)&psm[(16*w + g)     * 68 + nt*8 + 2*tg] =
                make_float2(rna(acc[mat][nt][0]), rna(acc[mat][nt][1]));
            *(float2*)&psm[(16*w + g + 8) * 68 + nt*8 + 2*tg] =
                make_float2(rna(acc[mat][nt][2]), rna(acc[mat][nt][3]));
        }
        __syncthreads();
        float* dst = (mat == 0) ? g_q : g_k;
        int row = tid >> 1, half = (tid & 1) * 32;
        #pragma unroll
        for (int i = 0; i < 8; i++) {
            float4 v = *(float4*)&psm[row * 68 + half + i * 4];
            *(float4*)&dst[(size_t)(m0 + row) * HH + half + i * 4] = v;
        }
    }

    __syncthreads();
    #pragma unroll
    for (int nt = 0; nt < 8; nt++) {   // psm as [64 d][132]
        psm[(nt*8 + 2*tg)     * 132 + 16*w + g]     = rna(acc[2][nt][0]);
        psm[(nt*8 + 2*tg + 1) * 132 + 16*w + g]     = rna(acc[2][nt][1]);
        psm[(nt*8 + 2*tg)     * 132 + 16*w + g + 8] = rna(acc[2][nt][2]);
        psm[(nt*8 + 2*tg + 1) * 132 + 16*w + g + 8] = rna(acc[2][nt][3]);
    }
    __syncthreads();
    {
        int d = tid >> 2, sh = (tid & 3) * 32;
        #pragma unroll
        for (int i = 0; i < 8; i++) {
            float4 v = *(float4*)&psm[d * 132 + sh + i * 4];
            *(float4*)&g_vt[((size_t)bq * HH + d) * SS + s0 + sh + i * 4] = v;
        }
    }
}

// ---------------------------------------------------------------------------
// Kernel 2: causal flash attention, tf32 mma.sync.
// 128 threads; q-tile 128 rows; kv tiles 64, cp.async double-buffered.
// Q fragments hoisted into registers (loop-invariant); P goes
// fragment->fragment via shuffles (no smem roundtrip).
// smem (floats): Qs 0 (128x68) | K buf0 8704 / buf1 13056 | V buf0 17408 /
// buf1 21760 (each 64x68). Total 26112 floats = 104448 B -> 2 CTAs/SM.
// ---------------------------------------------------------------------------
#define ATTN_SMEM (26112 * 4)

__global__ __launch_bounds__(128) void attn_kernel(float* __restrict__ out)
{
    extern __shared__ float sm[];
    const uint32_t SB = smem_u32(sm);

    const int tid  = threadIdx.x;
    const int w    = tid >> 5;
    const int lane = tid & 31;
    const int g    = lane >> 2;
    const int tg   = lane & 3;

    // --- load-balance remap: unpaired SM slots (pos 108-147) take the 40
    // heaviest q-tiles; paired slots (pos, pos+148) take complementary ranks.
    int pos = blockIdx.x, rank;
    if      (pos < 108) rank = 40 + pos;
    else if (pos < 148) rank = pos - 108;
    else                rank = 255 - (pos - 148);
    const int qt = 15 - (rank >> 4);
    const int b  = rank & 15;

    auto stageKV = [&](int kt2, int buf) {
        int row = tid >> 1, hh = (tid & 1) * 32;
        const float* ks = g_k + ((size_t)b * SS + kt2 * 64 + row) * HH + hh;
        uint32_t kd = SB + (8704 + buf * 4352 + row * 68 + hh) * 4;
        #pragma unroll
        for (int i = 0; i < 8; i++) CP16(kd + i * 16, ks + i * 4);
        const float* vs = g_vt + ((size_t)b * HH + row) * SS + kt2 * 64 + hh;
        uint32_t vd = SB + (17408 + buf * 4352 + row * 68 + hh) * 4;
        #pragma unroll
        for (int i = 0; i < 8; i++) CP16(vd + i * 16, vs + i * 4);
    };

    // Q (pre-rounded) via cp.async
    {
        const float* src = g_q + ((size_t)b * SS + qt * 128 + tid) * HH;
        uint32_t dst = SB + (tid * 68) * 4;
        #pragma unroll
        for (int i = 0; i < 16; i++) CP16(dst + i * 16, src + i * 4);
    }
    CP_COMMIT();
    stageKV(0, 0); CP_COMMIT();

    float oacc[2][8][4];
    #pragma unroll
    for (int m = 0; m < 2; m++)
        #pragma unroll
        for (int n = 0; n < 8; n++)
            #pragma unroll
            for (int i = 0; i < 4; i++) oacc[m][n][i] = 0.f;
    float lsum[2][2] = {{0.f, 0.f}, {0.f, 0.f}};
    float qf[8][2][4];   // Q fragments, loop-invariant

    const float scl = 1.0f / 64.0f;
    const int rbase = qt * 128 + 32 * w + g;
    const int ktmax = 2 * qt + 1;
    const float* Qs = sm;

    for (int kt = 0; kt <= ktmax; kt++) {
        __syncthreads();   // prior iter's reads of the refill buffers done
        if (kt + 1 <= ktmax) { stageKV(kt + 1, (kt + 1) & 1); CP_COMMIT(); CP_WAIT1(); }
        else                 { CP_WAIT0(); }
        __syncthreads();   // KV tile kt (and Q on kt=0) visible

        if (kt == 0) {     // hoist Q fragments once (conflict-free scalar LDS)
            #pragma unroll
            for (int ks = 0; ks < 8; ks++)
                #pragma unroll
                for (int mt = 0; mt < 2; mt++) {
                    int r = 32*w + 16*mt + g;
                    qf[ks][mt][0] = Qs[r       * 68 + ks*8 + tg];
                    qf[ks][mt][1] = Qs[(r + 8) * 68 + ks*8 + tg];
                    qf[ks][mt][2] = Qs[r       * 68 + ks*8 + tg + 4];
                    qf[ks][mt][3] = Qs[(r + 8) * 68 + ks*8 + tg + 4];
                }
        }

        const float* Ks = sm + 8704  + (kt & 1) * 4352;
        const float* Vt = sm + 17408 + (kt & 1) * 4352;

        // ---- S = Q K^T (A from registers, B conflict-free scalar LDS) ----
        float p[2][8][4];
        #pragma unroll
        for (int m = 0; m < 2; m++)
            #pragma unroll
            for (int n = 0; n < 8; n++)
                #pragma unroll
                for (int i = 0; i < 4; i++) p[m][n][i] = 0.f;

        #pragma unroll
        for (int ks = 0; ks < 8; ks++) {
            #pragma unroll
            for (int nt = 0; nt < 8; nt++) {
                float bb[2];
                bb[0] = Ks[(nt*8 + g) * 68 + ks*8 + tg];
                bb[1] = Ks[(nt*8 + g) * 68 + ks*8 + tg + 4];
                mma8(p[0][nt], qf[ks][0], bb);
                mma8(p[1][nt], qf[ks][1], bb);
            }
        }

        // ---- mask + exp (rna) in place ----
        #pragma unroll
        for (int mt = 0; mt < 2; mt++) {
            int rg0 = rbase + 16*mt;
            int rg1 = rg0 + 8;
            #pragma unroll
            for (int nt = 0; nt < 8; nt++) {
                int c0 = kt*64 + nt*8 + 2*tg;
                float p0 = (c0     <= rg0) ? rna(__expf(p[mt][nt][0] * scl)) : 0.f;
                float p1 = (c0 + 1 <= rg0) ? rna(__expf(p[mt][nt][1] * scl)) : 0.f;
                float p2 = (c0     <= rg1) ? rna(__expf(p[mt][nt][2] * scl)) : 0.f;
                float p3 = (c0 + 1 <= rg1) ? rna(__expf(p[mt][nt][3] * scl)) : 0.f;
                lsum[mt][0] += p0 + p1;
                lsum[mt][1] += p2 + p3;
                p[mt][nt][0] = p0; p[mt][nt][1] = p1;
                p[mt][nt][2] = p2; p[mt][nt][3] = p3;
            }
        }

        // ---- O += P V : C-fragment -> A-fragment via intra-quad shuffles ----
        {
            const int s0l = (lane & 28) | (tg >> 1);
            const int s1l = s0l + 2;
            const bool odd = (tg & 1);
            #pragma unroll
            for (int ks = 0; ks < 8; ks++) {
                float a[2][4];
                #pragma unroll
                for (int mt = 0; mt < 2; mt++) {
                    float c0 = p[mt][ks][0], c1 = p[mt][ks][1];
                    float c2 = p[mt][ks][2], c3 = p[mt][ks][3];
                    float v0 = __shfl_sync(0xffffffffu, c0, s0l);
                    float v1 = __shfl_sync(0xffffffffu, c1, s0l);
                    float v2 = __shfl_sync(0xffffffffu, c2, s0l);
                    float v3 = __shfl_sync(0xffffffffu, c3, s0l);
                    float u0 = __shfl_sync(0xffffffffu, c0, s1l);
                    float u1 = __shfl_sync(0xffffffffu, c1, s1l);
                    float u2 = __shfl_sync(0xffffffffu, c2, s1l);
                    float u3 = __shfl_sync(0xffffffffu, c3, s1l);
                    a[mt][0] = odd ? v1 : v0;   // row g,   col tg
                    a[mt][1] = odd ? v3 : v2;   // row g+8, col tg
                    a[mt][2] = odd ? u1 : u0;   // row g,   col tg+4
                    a[mt][3] = odd ? u3 : u2;   // row g+8, col tg+4
                }
                #pragma unroll
                for (int nt = 0; nt < 8; nt++) {
                    float bb[2];
                    bb[0] = Vt[(nt*8 + g) * 68 + ks*8 + tg];
                    bb[1] = Vt[(nt*8 + g) * 68 + ks*8 + tg + 4];
                    mma8(oacc[0][nt], a[0], bb);
                    mma8(oacc[1][nt], a[1], bb);
                }
            }
        }
    }

    // reduce l across the 4 quad lanes (same row group)
    #pragma unroll
    for (int mt = 0; mt < 2; mt++)
        #pragma unroll
        for (int h = 0; h < 2; h++) {
            float v = lsum[mt][h];
            v += __shfl_xor_sync(0xffffffffu, v, 1);
            v += __shfl_xor_sync(0xffffffffu, v, 2);
            lsum[mt][h] = v;
        }

    // normalize + write
    #pragma unroll
    for (int mt = 0; mt < 2; mt++) {
        float i0 = 1.0f / lsum[mt][0];
        float i1 = 1.0f / lsum[mt][1];
        int r = qt*128 + 32*w + 16*mt + g;
        float* o0 = out + ((size_t)b * SS + r)     * HH;
        float* o1 = out + ((size_t)b * SS + r + 8) * HH;
        #pragma unroll
        for (int nt = 0; nt < 8; nt++) {
            *(float2*)&o0[nt*8 + 2*tg] =
                make_float2(oacc[mt][nt][0] * i0, oacc[mt][nt][1] * i0);
            *(float2*)&o1[nt*8 + 2*tg] =
                make_float2(oacc[mt][nt][2] * i1, oacc[mt][nt][3] * i1);
        }
    }
}

// ---------------------------------------------------------------------------
extern "C" void kernel_launch(void* const* d_in, const int* in_sizes, int n_in,
                              void* d_out, int out_size)
{
    const float* x  = (const float*)d_in[0];
    const float* Wq = (const float*)d_in[1];
    const float* Wk = (const float*)d_in[2];
    const float* Wv = (const float*)d_in[3];
    float* out = (float*)d_out;
    (void)in_sizes; (void)n_in; (void)out_size;

    cudaFuncSetAttribute(proj_kernel, cudaFuncAttributeMaxDynamicSharedMemorySize,
                         PROJ_SMEM);
    cudaFuncSetAttribute(attn_kernel, cudaFuncAttributeMaxDynamicSharedMemorySize,
                         ATTN_SMEM);

    transpose_w<<<48, 128>>>(Wq, Wk, Wv);
    proj_kernel<<<MM / 128, 256, PROJ_SMEM>>>(x);
    attn_kernel<<<256, 128, ATTN_SMEM>>>(out);
}

// round 15
// speedup vs baseline: 1.5969x; 1.3155x over previous
#include <cuda_runtime.h>
#include <cstdint>

#define BB 16
#define SS 2048
#define DD 1024
#define HH 64
#define MM (BB*SS)

// Scratch (no cudaMalloc allowed). All pre-rounded to tf32 (rna) at producer.
__device__ float g_q [MM*HH];      // [b*2048+s][64]
__device__ float g_k [MM*HH];      // [b*2048+s][64]
__device__ float g_vt[MM*HH];      // [b*64+d][2048]  (V transposed)
__device__ float g_wt[3*HH*DD];    // [mat][n*1024+k] (W transposed)
__device__ float g_po[2*MM*HH];    // split-kv partial O (unnormalized)
__device__ float g_pl[2*MM];       // split-kv partial l

// ---------------------------------------------------------------------------
// helpers
// ---------------------------------------------------------------------------
static __device__ __forceinline__ float rna(float f) {
    uint32_t r;
    asm("cvt.rna.tf32.f32 %0, %1;" : "=r"(r) : "f"(f));
    return __uint_as_float(r);
}
static __device__ __forceinline__ uint32_t smem_u32(const void* p) {
    uint32_t a;
    asm("{ .reg .u64 t; cvta.to.shared.u64 t, %1; cvt.u32.u64 %0, t; }"
        : "=r"(a) : "l"(p));
    return a;
}
#define CP16(dst, src) \
    asm volatile("cp.async.ca.shared.global [%0], [%1], 16;" \
                 :: "r"(dst), "l"(src) : "memory")
#define CP_COMMIT() asm volatile("cp.async.commit_group;" ::: "memory")
#define CP_WAIT1()  asm volatile("cp.async.wait_group 1;" ::: "memory")
#define CP_WAIT0()  asm volatile("cp.async.wait_group 0;" ::: "memory")

// D += A(16x8) * B(8x8); tf32 inputs, f32 accum.
static __device__ __forceinline__ void mma8(float* d, const float* a, const float* b) {
    asm volatile(
        "mma.sync.aligned.m16n8k8.row.col.f32.tf32.tf32.f32 "
        "{%0,%1,%2,%3}, {%4,%5,%6,%7}, {%8,%9}, {%0,%1,%2,%3};"
        : "+f"(d[0]), "+f"(d[1]), "+f"(d[2]), "+f"(d[3])
        : "r"(__float_as_uint(a[0])), "r"(__float_as_uint(a[1])),
          "r"(__float_as_uint(a[2])), "r"(__float_as_uint(a[3])),
          "r"(__float_as_uint(b[0])), "r"(__float_as_uint(b[1])));
}

// ---------------------------------------------------------------------------
// Kernel 0: transpose + tf32-round W -> g_wt[mat][n*1024+k]
// ---------------------------------------------------------------------------
__global__ __launch_bounds__(128) void transpose_w(
    const float* __restrict__ Wq, const float* __restrict__ Wk,
    const float* __restrict__ Wv)
{
    int mat = blockIdx.x >> 4, kc = blockIdx.x & 15;
    const float* W = (mat == 0) ? Wq : (mat == 1) ? Wk : Wv;
    int tid = threadIdx.x;
    #pragma unroll
    for (int i = 0; i < 8; i++) {
        int lin = tid + i * 128;
        int k   = lin >> 4;
        int n4  = lin & 15;
        float4 v = *(const float4*)(W + (size_t)(kc * 64 + k) * HH + n4 * 4);
        int kg = kc * 64 + k;
        float* dst = g_wt + (size_t)mat * HH * DD;
        dst[(n4*4+0) * DD + kg] = rna(v.x);
        dst[(n4*4+1) * DD + kg] = rna(v.y);
        dst[(n4*4+2) * DD + kg] = rna(v.z);
        dst[(n4*4+3) * DD + kg] = rna(v.w);
    }
}

// ---------------------------------------------------------------------------
// Kernel 1: fused QKV projection, tf32 mma.sync, cp.async double-buffered.
// (unchanged from best-known config)
// ---------------------------------------------------------------------------
#define XSTR 36
#define PROJ_SMEM (23040 * 4)

__global__ __launch_bounds__(256) void proj_kernel(const float* __restrict__ x)
{
    extern __shared__ float psm[];
    const uint32_t SB = smem_u32(psm);

    const int tid  = threadIdx.x;
    const int w    = tid >> 5;
    const int lane = tid & 31;
    const int g    = lane >> 2;
    const int tg   = lane & 3;
    const int m0   = blockIdx.x * 128;

    auto stage = [&](int c, int buf) {
        {
            int row = tid >> 1, kq = (tid & 1) * 16;
            const float* src = x + (size_t)(m0 + row) * DD + c * 32 + kq;
            uint32_t dst = SB + (buf * 4608 + row * XSTR + kq) * 4;
            #pragma unroll
            for (int i = 0; i < 4; i++) CP16(dst + i * 16, src + i * 4);
        }
        {
            int n = tid >> 2, kq = (tid & 3) * 8;
            #pragma unroll
            for (int mat = 0; mat < 3; mat++) {
                const float* src = g_wt + (size_t)mat * HH * DD + (size_t)n * DD + c * 32 + kq;
                uint32_t dst = SB + (9216 + buf * 6912 + (mat * 64 + n) * XSTR + kq) * 4;
                CP16(dst, src);
                CP16(dst + 16, src + 4);
            }
        }
    };

    float acc[3][8][4];
    #pragma unroll
    for (int m = 0; m < 3; m++)
        #pragma unroll
        for (int n = 0; n < 8; n++)
            #pragma unroll
            for (int i = 0; i < 4; i++) acc[m][n][i] = 0.f;

    stage(0, 0); CP_COMMIT();

    for (int c = 0; c < 32; c++) {
        __syncthreads();
        if (c + 1 < 32) { stage(c + 1, (c + 1) & 1); CP_COMMIT(); CP_WAIT1(); }
        else            { CP_WAIT0(); }
        __syncthreads();

        const float* Xb = psm + (c & 1) * 4608;
        const float* Wb = psm + 9216 + (c & 1) * 6912;
        #pragma unroll
        for (int ks = 0; ks < 4; ks++) {
            float a[4];
            a[0] = rna(Xb[(16*w + g)     * XSTR + ks*8 + tg]);
            a[1] = rna(Xb[(16*w + g + 8) * XSTR + ks*8 + tg]);
            a[2] = rna(Xb[(16*w + g)     * XSTR + ks*8 + tg + 4]);
            a[3] = rna(Xb[(16*w + g + 8) * XSTR + ks*8 + tg + 4]);
            #pragma unroll
            for (int mat = 0; mat < 3; mat++)
                #pragma unroll
                for (int nt = 0; nt < 8; nt++) {
                    float bb[2];
                    bb[0] = Wb[(mat*64 + nt*8 + g) * XSTR + ks*8 + tg];
                    bb[1] = Wb[(mat*64 + nt*8 + g) * XSTR + ks*8 + tg + 4];
                    mma8(acc[mat][nt], a, bb);
                }
        }
    }

    const int bq = m0 >> 11;
    const int s0 = m0 & 2047;

    #pragma unroll
    for (int mat = 0; mat < 2; mat++) {
        __syncthreads();
        #pragma unroll
        for (int nt = 0; nt < 8; nt++) {
            *(float2*)&psm[(16*w + g)     * 68 + nt*8 + 2*tg] =
                make_float2(rna(acc[mat][nt][0]), rna(acc[mat][nt][1]));
            *(float2*)&psm[(16*w + g + 8) * 68 + nt*8 + 2*tg] =
                make_float2(rna(acc[mat][nt][2]), rna(acc[mat][nt][3]));
        }
        __syncthreads();
        float* dst = (mat == 0) ? g_q : g_k;
        int row = tid >> 1, half = (tid & 1) * 32;
        #pragma unroll
        for (int i = 0; i < 8; i++) {
            float4 v = *(float4*)&psm[row * 68 + half + i * 4];
            *(float4*)&dst[(size_t)(m0 + row) * HH + half + i * 4] = v;
        }
    }

    __syncthreads();
    #pragma unroll
    for (int nt = 0; nt < 8; nt++) {   // psm as [64 d][132]
        psm[(nt*8 + 2*tg)     * 132 + 16*w + g]     = rna(acc[2][nt][0]);
        psm[(nt*8 + 2*tg + 1) * 132 + 16*w + g]     = rna(acc[2][nt][1]);
        psm[(nt*8 + 2*tg)     * 132 + 16*w + g + 8] = rna(acc[2][nt][2]);
        psm[(nt*8 + 2*tg + 1) * 132 + 16*w + g + 8] = rna(acc[2][nt][3]);
    }
    __syncthreads();
    {
        int d = tid >> 2, sh = (tid & 3) * 32;
        #pragma unroll
        for (int i = 0; i < 8; i++) {
            float4 v = *(float4*)&psm[d * 132 + sh + i * 4];
            *(float4*)&g_vt[((size_t)bq * HH + d) * SS + s0 + sh + i * 4] = v;
        }
    }
}

// ---------------------------------------------------------------------------
// Kernel 2: causal flash attention, tf32 mma.sync, 2-way SPLIT-KV.
// 512 CTAs: rank = blockIdx.x (heavy-first); qt = 15-(rank>>5),
// half = (rank>>4)&1, b = rank&15. CTA processes kv tiles
// [half*(qt+1), (half+1)*(qt+1)), writing UNNORMALIZED O and l partials.
// smem (floats): Qs 0 (128x68) | K buf0 8704 / buf1 13056 | V buf0 17408 /
// buf1 21760 (each 64x68).
// ---------------------------------------------------------------------------
#define ATTN_SMEM (26112 * 4)

__global__ __launch_bounds__(128) void attn_kernel()
{
    extern __shared__ float sm[];
    const uint32_t SB = smem_u32(sm);

    const int tid  = threadIdx.x;
    const int w    = tid >> 5;
    const int lane = tid & 31;
    const int g    = lane >> 2;
    const int tg   = lane & 3;

    const int rank = blockIdx.x;
    const int qt   = 15 - (rank >> 5);     // heavy q-tiles first
    const int half = (rank >> 4) & 1;
    const int b    = rank & 15;
    const int ntile = qt + 1;
    const int kt0   = half * (qt + 1);

    auto stageKV = [&](int kt2, int buf) {
        int row = tid >> 1, hh = (tid & 1) * 32;
        const float* ks = g_k + ((size_t)b * SS + kt2 * 64 + row) * HH + hh;
        uint32_t kd = SB + (8704 + buf * 4352 + row * 68 + hh) * 4;
        #pragma unroll
        for (int i = 0; i < 8; i++) CP16(kd + i * 16, ks + i * 4);
        const float* vs = g_vt + ((size_t)b * HH + row) * SS + kt2 * 64 + hh;
        uint32_t vd = SB + (17408 + buf * 4352 + row * 68 + hh) * 4;
        #pragma unroll
        for (int i = 0; i < 8; i++) CP16(vd + i * 16, vs + i * 4);
    };

    // Q (pre-rounded) via cp.async
    {
        const float* src = g_q + ((size_t)b * SS + qt * 128 + tid) * HH;
        uint32_t dst = SB + (tid * 68) * 4;
        #pragma unroll
        for (int i = 0; i < 16; i++) CP16(dst + i * 16, src + i * 4);
    }
    CP_COMMIT();
    stageKV(kt0, 0); CP_COMMIT();

    float oacc[2][8][4];
    #pragma unroll
    for (int m = 0; m < 2; m++)
        #pragma unroll
        for (int n = 0; n < 8; n++)
            #pragma unroll
            for (int i = 0; i < 4; i++) oacc[m][n][i] = 0.f;
    float lsum[2][2] = {{0.f, 0.f}, {0.f, 0.f}};
    float qf[8][2][4];   // Q fragments, loop-invariant

    const float scl = 1.0f / 64.0f;
    const int rbase = qt * 128 + 32 * w + g;
    const float* Qs = sm;

    for (int i = 0; i < ntile; i++) {
        const int kt = kt0 + i;
        __syncthreads();   // prior iter's reads of the refill buffers done
        if (i + 1 < ntile) { stageKV(kt + 1, (i + 1) & 1); CP_COMMIT(); CP_WAIT1(); }
        else               { CP_WAIT0(); }
        __syncthreads();   // KV tile kt (and Q on i=0) visible

        if (i == 0) {      // hoist Q fragments once (conflict-free scalar LDS)
            #pragma unroll
            for (int ks = 0; ks < 8; ks++)
                #pragma unroll
                for (int mt = 0; mt < 2; mt++) {
                    int r = 32*w + 16*mt + g;
                    qf[ks][mt][0] = Qs[r       * 68 + ks*8 + tg];
                    qf[ks][mt][1] = Qs[(r + 8) * 68 + ks*8 + tg];
                    qf[ks][mt][2] = Qs[r       * 68 + ks*8 + tg + 4];
                    qf[ks][mt][3] = Qs[(r + 8) * 68 + ks*8 + tg + 4];
                }
        }

        const float* Ks = sm + 8704  + (i & 1) * 4352;
        const float* Vt = sm + 17408 + (i & 1) * 4352;

        // ---- S = Q K^T ----
        float p[2][8][4];
        #pragma unroll
        for (int m = 0; m < 2; m++)
            #pragma unroll
            for (int n = 0; n < 8; n++)
                #pragma unroll
                for (int ii = 0; ii < 4; ii++) p[m][n][ii] = 0.f;

        #pragma unroll
        for (int ks = 0; ks < 8; ks++) {
            #pragma unroll
            for (int nt = 0; nt < 8; nt++) {
                float bb[2];
                bb[0] = Ks[(nt*8 + g) * 68 + ks*8 + tg];
                bb[1] = Ks[(nt*8 + g) * 68 + ks*8 + tg + 4];
                mma8(p[0][nt], qf[ks][0], bb);
                mma8(p[1][nt], qf[ks][1], bb);
            }
        }

        // ---- mask + exp (rna) in place ----
        #pragma unroll
        for (int mt = 0; mt < 2; mt++) {
            int rg0 = rbase + 16*mt;
            int rg1 = rg0 + 8;
            #pragma unroll
            for (int nt = 0; nt < 8; nt++) {
                int c0 = kt*64 + nt*8 + 2*tg;
                float p0 = (c0     <= rg0) ? rna(__expf(p[mt][nt][0] * scl)) : 0.f;
                float p1 = (c0 + 1 <= rg0) ? rna(__expf(p[mt][nt][1] * scl)) : 0.f;
                float p2 = (c0     <= rg1) ? rna(__expf(p[mt][nt][2] * scl)) : 0.f;
                float p3 = (c0 + 1 <= rg1) ? rna(__expf(p[mt][nt][3] * scl)) : 0.f;
                lsum[mt][0] += p0 + p1;
                lsum[mt][1] += p2 + p3;
                p[mt][nt][0] = p0; p[mt][nt][1] = p1;
                p[mt][nt][2] = p2; p[mt][nt][3] = p3;
            }
        }

        // ---- O += P V : C-fragment -> A-fragment via intra-quad shuffles ----
        {
            const int s0l = (lane & 28) | (tg >> 1);
            const int s1l = s0l + 2;
            const bool odd = (tg & 1);
            #pragma unroll
            for (int ks = 0; ks < 8; ks++) {
                float a[2][4];
                #pragma unroll
                for (int mt = 0; mt < 2; mt++) {
                    float c0 = p[mt][ks][0], c1 = p[mt][ks][1];
                    float c2 = p[mt][ks][2], c3 = p[mt][ks][3];
                    float v0 = __shfl_sync(0xffffffffu, c0, s0l);
                    float v1 = __shfl_sync(0xffffffffu, c1, s0l);
                    float v2 = __shfl_sync(0xffffffffu, c2, s0l);
                    float v3 = __shfl_sync(0xffffffffu, c3, s0l);
                    float u0 = __shfl_sync(0xffffffffu, c0, s1l);
                    float u1 = __shfl_sync(0xffffffffu, c1, s1l);
                    float u2 = __shfl_sync(0xffffffffu, c2, s1l);
                    float u3 = __shfl_sync(0xffffffffu, c3, s1l);
                    a[mt][0] = odd ? v1 : v0;
                    a[mt][1] = odd ? v3 : v2;
                    a[mt][2] = odd ? u1 : u0;
                    a[mt][3] = odd ? u3 : u2;
                }
                #pragma unroll
                for (int nt = 0; nt < 8; nt++) {
                    float bb[2];
                    bb[0] = Vt[(nt*8 + g) * 68 + ks*8 + tg];
                    bb[1] = Vt[(nt*8 + g) * 68 + ks*8 + tg + 4];
                    mma8(oacc[0][nt], a[0], bb);
                    mma8(oacc[1][nt], a[1], bb);
                }
            }
        }
    }

    // reduce l across the 4 quad lanes (same row group)
    #pragma unroll
    for (int mt = 0; mt < 2; mt++)
        #pragma unroll
        for (int h = 0; h < 2; h++) {
            float v = lsum[mt][h];
            v += __shfl_xor_sync(0xffffffffu, v, 1);
            v += __shfl_xor_sync(0xffffffffu, v, 2);
            lsum[mt][h] = v;
        }

    // write UNNORMALIZED partials
    float* pob = g_po + (size_t)half * MM * HH;
    float* plb = g_pl + (size_t)half * MM;
    #pragma unroll
    for (int mt = 0; mt < 2; mt++) {
        int r = qt*128 + 32*w + 16*mt + g;
        size_t row0 = (size_t)b * SS + r;
        float* o0 = pob + row0 * HH;
        float* o1 = pob + (row0 + 8) * HH;
        #pragma unroll
        for (int nt = 0; nt < 8; nt++) {
            *(float2*)&o0[nt*8 + 2*tg] = make_float2(oacc[mt][nt][0], oacc[mt][nt][1]);
            *(float2*)&o1[nt*8 + 2*tg] = make_float2(oacc[mt][nt][2], oacc[mt][nt][3]);
        }
        if (tg == 0) {
            plb[row0]     = lsum[mt][0];
            plb[row0 + 8] = lsum[mt][1];
        }
    }
}

// ---------------------------------------------------------------------------
// Kernel 3: merge split-kv partials: out = (O0+O1) / (l0+l1)
// ---------------------------------------------------------------------------
__global__ __launch_bounds__(128) void merge_kernel(float* __restrict__ out)
{
    int row = blockIdx.x * 128 + threadIdx.x;   // 0..32767
    float inv = 1.0f / (g_pl[row] + g_pl[MM + row]);
    const float* p0 = g_po + (size_t)row * HH;
    const float* p1 = g_po + (size_t)MM * HH + (size_t)row * HH;
    float* o = out + (size_t)row * HH;
    #pragma unroll
    for (int d = 0; d < HH; d += 4) {
        float4 a  = *(const float4*)(p0 + d);
        float4 bv = *(const float4*)(p1 + d);
        *(float4*)(o + d) = make_float4((a.x + bv.x) * inv, (a.y + bv.y) * inv,
                                        (a.z + bv.z) * inv, (a.w + bv.w) * inv);
    }
}

// ---------------------------------------------------------------------------
extern "C" void kernel_launch(void* const* d_in, const int* in_sizes, int n_in,
                              void* d_out, int out_size)
{
    const float* x  = (const float*)d_in[0];
    const float* Wq = (const float*)d_in[1];
    const float* Wk = (const float*)d_in[2];
    const float* Wv = (const float*)d_in[3];
    float* out = (float*)d_out;
    (void)in_sizes; (void)n_in; (void)out_size;

    cudaFuncSetAttribute(proj_kernel, cudaFuncAttributeMaxDynamicSharedMemorySize,
                         PROJ_SMEM);
    cudaFuncSetAttribute(attn_kernel, cudaFuncAttributeMaxDynamicSharedMemorySize,
                         ATTN_SMEM);

    transpose_w<<<48, 128>>>(Wq, Wk, Wv);
    proj_kernel<<<MM / 128, 256, PROJ_SMEM>>>(x);
    attn_kernel<<<512, 128, ATTN_SMEM>>>();
    merge_kernel<<<MM / 128, 128>>>(out);
}

// round 16
// speedup vs baseline: 1.7010x; 1.0652x over previous
#include <cuda_runtime.h>
#include <cstdint>

#define BB 16
#define SS 2048
#define DD 1024
#define HH 64
#define MM (BB*SS)

// Scratch (no cudaMalloc allowed). All pre-rounded to tf32 (rna) at producer.
__device__ float g_q [MM*HH];      // [b*2048+s][64]
__device__ float g_k [MM*HH];      // [b*2048+s][64]
__device__ float g_vt[MM*HH];      // [b*64+d][2048]  (V transposed)
__device__ float g_wt[3*HH*DD];    // [mat][n*1024+k] (W transposed)
__device__ float g_po[2*MM*HH];    // split-kv partial O (unnormalized)
__device__ float g_pl[2*MM];       // split-kv partial l

// ---------------------------------------------------------------------------
// helpers
// ---------------------------------------------------------------------------
static __device__ __forceinline__ float rna(float f) {
    uint32_t r;
    asm("cvt.rna.tf32.f32 %0, %1;" : "=r"(r) : "f"(f));
    return __uint_as_float(r);
}
static __device__ __forceinline__ uint32_t smem_u32(const void* p) {
    uint32_t a;
    asm("{ .reg .u64 t; cvta.to.shared.u64 t, %1; cvt.u32.u64 %0, t; }"
        : "=r"(a) : "l"(p));
    return a;
}
#define CP16(dst, src) \
    asm volatile("cp.async.ca.shared.global [%0], [%1], 16;" \
                 :: "r"(dst), "l"(src) : "memory")
#define CP_COMMIT() asm volatile("cp.async.commit_group;" ::: "memory")
#define CP_WAIT1()  asm volatile("cp.async.wait_group 1;" ::: "memory")
#define CP_WAIT0()  asm volatile("cp.async.wait_group 0;" ::: "memory")

// D += A(16x8) * B(8x8); tf32 inputs, f32 accum.
static __device__ __forceinline__ void mma8(float* d, const float* a, const float* b) {
    asm volatile(
        "mma.sync.aligned.m16n8k8.row.col.f32.tf32.tf32.f32 "
        "{%0,%1,%2,%3}, {%4,%5,%6,%7}, {%8,%9}, {%0,%1,%2,%3};"
        : "+f"(d[0]), "+f"(d[1]), "+f"(d[2]), "+f"(d[3])
        : "r"(__float_as_uint(a[0])), "r"(__float_as_uint(a[1])),
          "r"(__float_as_uint(a[2])), "r"(__float_as_uint(a[3])),
          "r"(__float_as_uint(b[0])), "r"(__float_as_uint(b[1])));
}

// ---------------------------------------------------------------------------
// Kernel 0: transpose + tf32-round W -> g_wt[mat][n*1024+k]
// ---------------------------------------------------------------------------
__global__ __launch_bounds__(128) void transpose_w(
    const float* __restrict__ Wq, const float* __restrict__ Wk,
    const float* __restrict__ Wv)
{
    int mat = blockIdx.x >> 4, kc = blockIdx.x & 15;
    const float* W = (mat == 0) ? Wq : (mat == 1) ? Wk : Wv;
    int tid = threadIdx.x;
    #pragma unroll
    for (int i = 0; i < 8; i++) {
        int lin = tid + i * 128;
        int k   = lin >> 4;
        int n4  = lin & 15;
        float4 v = *(const float4*)(W + (size_t)(kc * 64 + k) * HH + n4 * 4);
        int kg = kc * 64 + k;
        float* dst = g_wt + (size_t)mat * HH * DD;
        dst[(n4*4+0) * DD + kg] = rna(v.x);
        dst[(n4*4+1) * DD + kg] = rna(v.y);
        dst[(n4*4+2) * DD + kg] = rna(v.z);
        dst[(n4*4+3) * DD + kg] = rna(v.w);
    }
}

// ---------------------------------------------------------------------------
// Kernel 1: fused QKV projection, tf32 mma.sync, cp.async double-buffered.
// 512 threads (16 warps): warp = 16 rows (wr=w&7) x 96 cols (wn=w>>3 ->
// nt 4*wn..4*wn+3 per mat). K chunks of 32.
// dyn smem (floats): X buf0 0 / buf1 4608 (128x36) | W buf0 9216 / buf1 16128
// (192x36). Epilogue reuses [0..8704).
// ---------------------------------------------------------------------------
#define XSTR 36
#define PROJ_SMEM (23040 * 4)

__global__ __launch_bounds__(512) void proj_kernel(const float* __restrict__ x)
{
    extern __shared__ float psm[];
    const uint32_t SB = smem_u32(psm);

    const int tid  = threadIdx.x;
    const int w    = tid >> 5;
    const int lane = tid & 31;
    const int g    = lane >> 2;
    const int tg   = lane & 3;
    const int wr   = w & 7;     // row-tile 16*wr
    const int wn   = w >> 3;    // nt offset 4*wn
    const int m0   = blockIdx.x * 128;

    auto stage = [&](int c, int buf) {
        {   // X chunk: 128 x 32 = 1024 float4, 2 per thread
            #pragma unroll
            for (int i = 0; i < 2; i++) {
                int lin = tid + i * 512;
                int row = lin >> 3, c4 = lin & 7;
                const float* src = x + (size_t)(m0 + row) * DD + c * 32 + c4 * 4;
                CP16(SB + (buf * 4608 + row * XSTR + c4 * 4) * 4, src);
            }
        }
        {   // W chunks: 3 x 64 x 32 = 1536 float4, 3 per thread
            #pragma unroll
            for (int i = 0; i < 3; i++) {
                int lin = tid + i * 512;
                int mat = lin >> 9, rem = lin & 511;
                int n = rem >> 3, c4 = rem & 7;
                const float* src = g_wt + (size_t)mat * HH * DD + (size_t)n * DD + c * 32 + c4 * 4;
                CP16(SB + (9216 + buf * 6912 + (mat * 64 + n) * XSTR + c4 * 4) * 4, src);
            }
        }
    };

    float acc[3][4][4];
    #pragma unroll
    for (int m = 0; m < 3; m++)
        #pragma unroll
        for (int n = 0; n < 4; n++)
            #pragma unroll
            for (int i = 0; i < 4; i++) acc[m][n][i] = 0.f;

    stage(0, 0); CP_COMMIT();

    for (int c = 0; c < 32; c++) {
        __syncthreads();
        if (c + 1 < 32) { stage(c + 1, (c + 1) & 1); CP_COMMIT(); CP_WAIT1(); }
        else            { CP_WAIT0(); }
        __syncthreads();

        const float* Xb = psm + (c & 1) * 4608;
        const float* Wb = psm + 9216 + (c & 1) * 6912;
        const int r = 16 * wr + g;
        #pragma unroll
        for (int ks = 0; ks < 4; ks++) {
            float a[4];
            a[0] = rna(Xb[r       * XSTR + ks*8 + tg]);
            a[1] = rna(Xb[(r + 8) * XSTR + ks*8 + tg]);
            a[2] = rna(Xb[r       * XSTR + ks*8 + tg + 4]);
            a[3] = rna(Xb[(r + 8) * XSTR + ks*8 + tg + 4]);
            #pragma unroll
            for (int mat = 0; mat < 3; mat++)
                #pragma unroll
                for (int nti = 0; nti < 4; nti++) {
                    float bb[2];
                    int wrow = mat*64 + (4*wn + nti)*8 + g;
                    bb[0] = Wb[wrow * XSTR + ks*8 + tg];
                    bb[1] = Wb[wrow * XSTR + ks*8 + tg + 4];
                    mma8(acc[mat][nti], a, bb);
                }
        }
    }

    // ---- epilogue: rna-round everything (consumed only as tf32 inputs) ----
    const int bq = m0 >> 11;
    const int s0 = m0 & 2047;

    #pragma unroll
    for (int mat = 0; mat < 2; mat++) {
        __syncthreads();
        #pragma unroll
        for (int nti = 0; nti < 4; nti++) {
            int dbase = (4*wn + nti) * 8;
            int r = 16*wr + g;
            *(float2*)&psm[r       * 68 + dbase + 2*tg] =
                make_float2(rna(acc[mat][nti][0]), rna(acc[mat][nti][1]));
            *(float2*)&psm[(r + 8) * 68 + dbase + 2*tg] =
                make_float2(rna(acc[mat][nti][2]), rna(acc[mat][nti][3]));
        }
        __syncthreads();
        float* dst = (mat == 0) ? g_q : g_k;
        int row = tid >> 2, q4 = (tid & 3) * 16;
        #pragma unroll
        for (int i = 0; i < 4; i++) {
            float4 v = *(float4*)&psm[row * 68 + q4 + i * 4];
            *(float4*)&dst[(size_t)(m0 + row) * HH + q4 + i * 4] = v;
        }
    }

    __syncthreads();
    {   // V transposed staging: psm as [64 d][132]
        int sp0 = 16*wr + g;
        int sp1 = sp0 + 8;
        #pragma unroll
        for (int nti = 0; nti < 4; nti++) {
            int dbase = (4*wn + nti) * 8;
            psm[(dbase + 2*tg)     * 132 + sp0] = rna(acc[2][nti][0]);
            psm[(dbase + 2*tg + 1) * 132 + sp0] = rna(acc[2][nti][1]);
            psm[(dbase + 2*tg)     * 132 + sp1] = rna(acc[2][nti][2]);
            psm[(dbase + 2*tg + 1) * 132 + sp1] = rna(acc[2][nti][3]);
        }
    }
    __syncthreads();
    {
        int d = tid >> 3, sc = (tid & 7) * 16;
        #pragma unroll
        for (int i = 0; i < 4; i++) {
            float4 v = *(float4*)&psm[d * 132 + sc + i * 4];
            *(float4*)&g_vt[((size_t)bq * HH + d) * SS + s0 + sc + i * 4] = v;
        }
    }
}

// ---------------------------------------------------------------------------
// Kernel 2: causal flash attention, tf32 mma.sync, 2-way SPLIT-KV.
// (unchanged from R15 best)
// ---------------------------------------------------------------------------
#define ATTN_SMEM (26112 * 4)

__global__ __launch_bounds__(128) void attn_kernel()
{
    extern __shared__ float sm[];
    const uint32_t SB = smem_u32(sm);

    const int tid  = threadIdx.x;
    const int w    = tid >> 5;
    const int lane = tid & 31;
    const int g    = lane >> 2;
    const int tg   = lane & 3;

    const int rank = blockIdx.x;
    const int qt   = 15 - (rank >> 5);     // heavy q-tiles first
    const int half = (rank >> 4) & 1;
    const int b    = rank & 15;
    const int ntile = qt + 1;
    const int kt0   = half * (qt + 1);

    auto stageKV = [&](int kt2, int buf) {
        int row = tid >> 1, hh = (tid & 1) * 32;
        const float* ks = g_k + ((size_t)b * SS + kt2 * 64 + row) * HH + hh;
        uint32_t kd = SB + (8704 + buf * 4352 + row * 68 + hh) * 4;
        #pragma unroll
        for (int i = 0; i < 8; i++) CP16(kd + i * 16, ks + i * 4);
        const float* vs = g_vt + ((size_t)b * HH + row) * SS + kt2 * 64 + hh;
        uint32_t vd = SB + (17408 + buf * 4352 + row * 68 + hh) * 4;
        #pragma unroll
        for (int i = 0; i < 8; i++) CP16(vd + i * 16, vs + i * 4);
    };

    // Q (pre-rounded) via cp.async
    {
        const float* src = g_q + ((size_t)b * SS + qt * 128 + tid) * HH;
        uint32_t dst = SB + (tid * 68) * 4;
        #pragma unroll
        for (int i = 0; i < 16; i++) CP16(dst + i * 16, src + i * 4);
    }
    CP_COMMIT();
    stageKV(kt0, 0); CP_COMMIT();

    float oacc[2][8][4];
    #pragma unroll
    for (int m = 0; m < 2; m++)
        #pragma unroll
        for (int n = 0; n < 8; n++)
            #pragma unroll
            for (int i = 0; i < 4; i++) oacc[m][n][i] = 0.f;
    float lsum[2][2] = {{0.f, 0.f}, {0.f, 0.f}};
    float qf[8][2][4];   // Q fragments, loop-invariant

    const float scl = 1.0f / 64.0f;
    const int rbase = qt * 128 + 32 * w + g;
    const float* Qs = sm;

    for (int i = 0; i < ntile; i++) {
        const int kt = kt0 + i;
        __syncthreads();
        if (i + 1 < ntile) { stageKV(kt + 1, (i + 1) & 1); CP_COMMIT(); CP_WAIT1(); }
        else               { CP_WAIT0(); }
        __syncthreads();

        if (i == 0) {      // hoist Q fragments once (conflict-free scalar LDS)
            #pragma unroll
            for (int ks = 0; ks < 8; ks++)
                #pragma unroll
                for (int mt = 0; mt < 2; mt++) {
                    int r = 32*w + 16*mt + g;
                    qf[ks][mt][0] = Qs[r       * 68 + ks*8 + tg];
                    qf[ks][mt][1] = Qs[(r + 8) * 68 + ks*8 + tg];
                    qf[ks][mt][2] = Qs[r       * 68 + ks*8 + tg + 4];
                    qf[ks][mt][3] = Qs[(r + 8) * 68 + ks*8 + tg + 4];
                }
        }

        const float* Ks = sm + 8704  + (i & 1) * 4352;
        const float* Vt = sm + 17408 + (i & 1) * 4352;

        // ---- S = Q K^T ----
        float p[2][8][4];
        #pragma unroll
        for (int m = 0; m < 2; m++)
            #pragma unroll
            for (int n = 0; n < 8; n++)
                #pragma unroll
                for (int ii = 0; ii < 4; ii++) p[m][n][ii] = 0.f;

        #pragma unroll
        for (int ks = 0; ks < 8; ks++) {
            #pragma unroll
            for (int nt = 0; nt < 8; nt++) {
                float bb[2];
                bb[0] = Ks[(nt*8 + g) * 68 + ks*8 + tg];
                bb[1] = Ks[(nt*8 + g) * 68 + ks*8 + tg + 4];
                mma8(p[0][nt], qf[ks][0], bb);
                mma8(p[1][nt], qf[ks][1], bb);
            }
        }

        // ---- mask + exp (rna) in place ----
        #pragma unroll
        for (int mt = 0; mt < 2; mt++) {
            int rg0 = rbase + 16*mt;
            int rg1 = rg0 + 8;
            #pragma unroll
            for (int nt = 0; nt < 8; nt++) {
                int c0 = kt*64 + nt*8 + 2*tg;
                float p0 = (c0     <= rg0) ? rna(__expf(p[mt][nt][0] * scl)) : 0.f;
                float p1 = (c0 + 1 <= rg0) ? rna(__expf(p[mt][nt][1] * scl)) : 0.f;
                float p2 = (c0     <= rg1) ? rna(__expf(p[mt][nt][2] * scl)) : 0.f;
                float p3 = (c0 + 1 <= rg1) ? rna(__expf(p[mt][nt][3] * scl)) : 0.f;
                lsum[mt][0] += p0 + p1;
                lsum[mt][1] += p2 + p3;
                p[mt][nt][0] = p0; p[mt][nt][1] = p1;
                p[mt][nt][2] = p2; p[mt][nt][3] = p3;
            }
        }

        // ---- O += P V : C-fragment -> A-fragment via intra-quad shuffles ----
        {
            const int s0l = (lane & 28) | (tg >> 1);
            const int s1l = s0l + 2;
            const bool odd = (tg & 1);
            #pragma unroll
            for (int ks = 0; ks < 8; ks++) {
                float a[2][4];
                #pragma unroll
                for (int mt = 0; mt < 2; mt++) {
                    float c0 = p[mt][ks][0], c1 = p[mt][ks][1];
                    float c2 = p[mt][ks][2], c3 = p[mt][ks][3];
                    float v0 = __shfl_sync(0xffffffffu, c0, s0l);
                    float v1 = __shfl_sync(0xffffffffu, c1, s0l);
                    float v2 = __shfl_sync(0xffffffffu, c2, s0l);
                    float v3 = __shfl_sync(0xffffffffu, c3, s0l);
                    float u0 = __shfl_sync(0xffffffffu, c0, s1l);
                    float u1 = __shfl_sync(0xffffffffu, c1, s1l);
                    float u2 = __shfl_sync(0xffffffffu, c2, s1l);
                    float u3 = __shfl_sync(0xffffffffu, c3, s1l);
                    a[mt][0] = odd ? v1 : v0;
                    a[mt][1] = odd ? v3 : v2;
                    a[mt][2] = odd ? u1 : u0;
                    a[mt][3] = odd ? u3 : u2;
                }
                #pragma unroll
                for (int nt = 0; nt < 8; nt++) {
                    float bb[2];
                    bb[0] = Vt[(nt*8 + g) * 68 + ks*8 + tg];
                    bb[1] = Vt[(nt*8 + g) * 68 + ks*8 + tg + 4];
                    mma8(oacc[0][nt], a[0], bb);
                    mma8(oacc[1][nt], a[1], bb);
                }
            }
        }
    }

    // reduce l across the 4 quad lanes (same row group)
    #pragma unroll
    for (int mt = 0; mt < 2; mt++)
        #pragma unroll
        for (int h = 0; h < 2; h++) {
            float v = lsum[mt][h];
            v += __shfl_xor_sync(0xffffffffu, v, 1);
            v += __shfl_xor_sync(0xffffffffu, v, 2);
            lsum[mt][h] = v;
        }

    // write UNNORMALIZED partials
    float* pob = g_po + (size_t)half * MM * HH;
    float* plb = g_pl + (size_t)half * MM;
    #pragma unroll
    for (int mt = 0; mt < 2; mt++) {
        int r = qt*128 + 32*w + 16*mt + g;
        size_t row0 = (size_t)b * SS + r;
        float* o0 = pob + row0 * HH;
        float* o1 = pob + (row0 + 8) * HH;
        #pragma unroll
        for (int nt = 0; nt < 8; nt++) {
            *(float2*)&o0[nt*8 + 2*tg] = make_float2(oacc[mt][nt][0], oacc[mt][nt][1]);
            *(float2*)&o1[nt*8 + 2*tg] = make_float2(oacc[mt][nt][2], oacc[mt][nt][3]);
        }
        if (tg == 0) {
            plb[row0]     = lsum[mt][0];
            plb[row0 + 8] = lsum[mt][1];
        }
    }
}

// ---------------------------------------------------------------------------
// Kernel 3: merge split-kv partials: out = (O0+O1) / (l0+l1)
// ---------------------------------------------------------------------------
__global__ __launch_bounds__(128) void merge_kernel(float* __restrict__ out)
{
    int row = blockIdx.x * 128 + threadIdx.x;   // 0..32767
    float inv = 1.0f / (g_pl[row] + g_pl[MM + row]);
    const float* p0 = g_po + (size_t)row * HH;
    const float* p1 = g_po + (size_t)MM * HH + (size_t)row * HH;
    float* o = out + (size_t)row * HH;
    #pragma unroll
    for (int d = 0; d < HH; d += 4) {
        float4 a  = *(const float4*)(p0 + d);
        float4 bv = *(const float4*)(p1 + d);
        *(float4*)(o + d) = make_float4((a.x + bv.x) * inv, (a.y + bv.y) * inv,
                                        (a.z + bv.z) * inv, (a.w + bv.w) * inv);
    }
}

// ---------------------------------------------------------------------------
extern "C" void kernel_launch(void* const* d_in, const int* in_sizes, int n_in,
                              void* d_out, int out_size)
{
    const float* x  = (const float*)d_in[0];
    const float* Wq = (const float*)d_in[1];
    const float* Wk = (const float*)d_in[2];
    const float* Wv = (const float*)d_in[3];
    float* out = (float*)d_out;
    (void)in_sizes; (void)n_in; (void)out_size;

    cudaFuncSetAttribute(proj_kernel, cudaFuncAttributeMaxDynamicSharedMemorySize,
                         PROJ_SMEM);
    cudaFuncSetAttribute(attn_kernel, cudaFuncAttributeMaxDynamicSharedMemorySize,
                         ATTN_SMEM);

    transpose_w<<<48, 128>>>(Wq, Wk, Wv);
    proj_kernel<<<MM / 128, 512, PROJ_SMEM>>>(x);
    attn_kernel<<<512, 128, ATTN_SMEM>>>();
    merge_kernel<<<MM / 128, 128>>>(out);
}